// round 2
// baseline (speedup 1.0000x reference)
#include <cuda_runtime.h>
#include <cstdint>

// B[r,f,n] = sum_m CG[r,m] * A[f,m,n]   (fused over r-groups: r<8 -> out0, r>=8 -> out1)
// A: [F, M, 1024] f32. CG0: [8, M], CG1: [24, M].
// out0: [8, F, 1024], out1: [24, F, 1024] (row-major, contiguous in d_out per entry).
//
// Thread: one f, 2 consecutive n (one f32x2 lane pair). 32 packed accumulators.
// CG in shared, duplicated into both 32-bit halves, layout [m][r] -> broadcast LDS.128.

template <int M>
__global__ void __launch_bounds__(256, 2)
ace_sym_kernel(const float* __restrict__ A,
               const float* __restrict__ cg0,   // [8, M]
               const float* __restrict__ cg1,   // [24, M]
               float* __restrict__ out0,        // [8, F, 1024]
               float* __restrict__ out1,        // [24, F, 1024]
               int F)
{
    __shared__ __align__(16) unsigned long long scg[M * 32];  // [m][r], value duplicated in both halves

    const int tid = threadIdx.x;

    // Stage CG into shared, duplicated for f32x2.
    for (int i = tid; i < M * 32; i += 256) {
        const int m = i >> 5;
        const int r = i & 31;
        const float v = (r < 8) ? cg0[r * M + m] : cg1[(r - 8) * M + m];
        const unsigned int b = __float_as_uint(v);
        scg[i] = ((unsigned long long)b << 32) | (unsigned long long)b;
    }
    __syncthreads();

    const int f  = blockIdx.y;
    const int n0 = (blockIdx.x * 256 + tid) * 2;   // 2 floats per thread

    // A[f, m, n] : element ((f*M + m)*1024 + n). As u64 (float pairs): stride per m = 512.
    const unsigned long long* __restrict__ aptr =
        reinterpret_cast<const unsigned long long*>(A + ((size_t)f * M) * 1024 + n0);

    unsigned long long acc[32];
#pragma unroll
    for (int r = 0; r < 32; ++r) acc[r] = 0ull;

    // 4-deep prefetch ring (M >= 9 always).
    unsigned long long abuf[4];
#pragma unroll
    for (int i = 0; i < 4; ++i) abuf[i] = aptr[(size_t)i * 512];

#pragma unroll 4
    for (int m = 0; m < M; ++m) {
        const unsigned long long a2 = abuf[m & 3];
        if (m + 4 < M) abuf[m & 3] = aptr[(size_t)(m + 4) * 512];

        const ulonglong2* __restrict__ cgp =
            reinterpret_cast<const ulonglong2*>(&scg[m * 32]);
#pragma unroll
        for (int rp = 0; rp < 16; ++rp) {
            const ulonglong2 c = cgp[rp];   // two duplicated coefficients (r = 2rp, 2rp+1)
            asm("fma.rn.f32x2 %0, %1, %2, %0;" : "+l"(acc[2 * rp])     : "l"(a2), "l"(c.x));
            asm("fma.rn.f32x2 %0, %1, %2, %0;" : "+l"(acc[2 * rp + 1]) : "l"(a2), "l"(c.y));
        }
    }

    const size_t col = (size_t)f * 1024 + n0;
#pragma unroll
    for (int r = 0; r < 8; ++r)
        *reinterpret_cast<unsigned long long*>(out0 + ((size_t)r * F) * 1024 + col) = acc[r];
#pragma unroll
    for (int r = 0; r < 24; ++r)
        *reinterpret_cast<unsigned long long*>(out1 + ((size_t)r * F) * 1024 + col) = acc[r + 8];
}

extern "C" void kernel_launch(void* const* d_in, const int* in_sizes, int n_in,
                              void* d_out, int out_size)
{
    (void)in_sizes; (void)n_in; (void)out_size;

    const float* A2_l11  = (const float*)d_in[0];   // [1024, 9, 1024]
    const float* A2_l22  = (const float*)d_in[1];   // [1024, 25, 1024]
    const float* A2_l33  = (const float*)d_in[2];   // [1024, 49, 1024]
    const float* A3_l111 = (const float*)d_in[3];   // [512, 27, 1024]
    const float* A3_l211 = (const float*)d_in[4];   // [512, 45, 1024]

    const float* CG0_2_l11  = (const float*)d_in[5];
    const float* CG0_2_l22  = (const float*)d_in[6];
    const float* CG0_2_l33  = (const float*)d_in[7];
    const float* CG0_3_l111 = (const float*)d_in[8];
    const float* CG0_3_l211 = (const float*)d_in[9];
    const float* CG1_2_l11  = (const float*)d_in[10];
    const float* CG1_2_l22  = (const float*)d_in[11];
    const float* CG1_2_l33  = (const float*)d_in[12];
    const float* CG1_3_l111 = (const float*)d_in[13];
    const float* CG1_3_l211 = (const float*)d_in[14];

    float* out = (float*)d_out;

    // Output layout: concatenation of
    //   b0: [8,1024,1024] x3, [8,512,1024] x2
    //   b1: [24,1024,1024] x3, [24,512,1024] x2
    float* o0_l11  = out + 0;
    float* o0_l22  = out + 8388608;     //  8*1024*1024
    float* o0_l33  = out + 16777216;
    float* o0_l111 = out + 25165824;
    float* o0_l211 = out + 29360128;    // +8*512*1024
    float* o1_l11  = out + 33554432;
    float* o1_l22  = out + 58720256;    // +24*1024*1024
    float* o1_l33  = out + 83886080;
    float* o1_l111 = out + 109051904;
    float* o1_l211 = out + 121634816;   // +24*512*1024

    const dim3 blk(256);
    // grid.x = 1024 n / (256 threads * 2 floats) = 2 ; grid.y = F
    ace_sym_kernel< 9><<<dim3(2, 1024), blk>>>(A2_l11,  CG0_2_l11,  CG1_2_l11,  o0_l11,  o1_l11,  1024);
    ace_sym_kernel<25><<<dim3(2, 1024), blk>>>(A2_l22,  CG0_2_l22,  CG1_2_l22,  o0_l22,  o1_l22,  1024);
    ace_sym_kernel<49><<<dim3(2, 1024), blk>>>(A2_l33,  CG0_2_l33,  CG1_2_l33,  o0_l33,  o1_l33,  1024);
    ace_sym_kernel<27><<<dim3(2,  512), blk>>>(A3_l111, CG0_3_l111, CG1_3_l111, o0_l111, o1_l111,  512);
    ace_sym_kernel<45><<<dim3(2,  512), blk>>>(A3_l211, CG0_3_l211, CG1_3_l211, o0_l211, o1_l211,  512);
}

// round 5
// speedup vs baseline: 1.0934x; 1.0934x over previous
#include <cuda_runtime.h>
#include <cstdint>

// B[r,f,n] = sum_m CG[r,m] * A[f,m,n]
// A: [F, M, 1024] f32. CG0: [8, M], CG1: [24, M]. 32 total r rows.
// r split into 2 groups of 16 (blockIdx.x & 1) -> 16 u64 accs/thread (32 regs),
// no spills, occupancy 3 CTAs/SM. Sibling r-group re-reads A from L2.

template <int M>
__global__ void __launch_bounds__(256, 3)
ace_sym_kernel(const float* __restrict__ A,
               const float* __restrict__ cg0,   // [8, M]
               const float* __restrict__ cg1,   // [24, M]
               float* __restrict__ out0,        // [8, F, 1024]
               float* __restrict__ out1,        // [24, F, 1024]
               int F)
{
    __shared__ __align__(16) unsigned long long scg[M * 16];  // [m][16 local r], dup'd halves

    const int tid   = threadIdx.x;
    const int g     = blockIdx.x & 1;        // r-group: 0 -> r 0..15, 1 -> r 16..31
    const int ntile = blockIdx.x >> 1;       // n-tile: 0 or 1 (512 floats each)
    const int rbase = g << 4;

    // Stage this group's CG into shared, duplicated into both f32x2 lanes.
    for (int i = tid; i < M * 16; i += 256) {
        const int m  = i >> 4;
        const int r  = i & 15;
        const int rg = rbase + r;
        const float v = (rg < 8) ? cg0[rg * M + m] : cg1[(rg - 8) * M + m];
        const unsigned int b = __float_as_uint(v);
        scg[i] = ((unsigned long long)b << 32) | (unsigned long long)b;
    }
    __syncthreads();

    const int f  = blockIdx.y;
    const int n0 = (ntile * 256 + tid) * 2;  // 2 floats per thread

    // A[f, m, n]: as u64 pairs, stride per m = 512.
    const unsigned long long* __restrict__ aptr =
        reinterpret_cast<const unsigned long long*>(A + ((size_t)f * M) * 1024 + n0);

    unsigned long long acc[16];
#pragma unroll
    for (int r = 0; r < 16; ++r) acc[r] = 0ull;

    // 4-deep prefetch ring (M >= 9 always).
    unsigned long long abuf[4];
#pragma unroll
    for (int i = 0; i < 4; ++i) abuf[i] = aptr[(size_t)i * 512];

#pragma unroll 4
    for (int m = 0; m < M; ++m) {
        const unsigned long long a2 = abuf[m & 3];
        if (m + 4 < M) abuf[m & 3] = aptr[(size_t)(m + 4) * 512];

        const ulonglong2* __restrict__ cgp =
            reinterpret_cast<const ulonglong2*>(&scg[m * 16]);
#pragma unroll
        for (int rp = 0; rp < 8; ++rp) {
            const ulonglong2 c = cgp[rp];   // two duplicated coefficients
            asm("fma.rn.f32x2 %0, %1, %2, %0;" : "+l"(acc[2 * rp])     : "l"(a2), "l"(c.x));
            asm("fma.rn.f32x2 %0, %1, %2, %0;" : "+l"(acc[2 * rp + 1]) : "l"(a2), "l"(c.y));
        }
    }

    // Streaming stores (.cs) — keep L2 for the sibling r-group's A re-read.
    const size_t col = (size_t)f * 1024 + n0;
#pragma unroll
    for (int r = 0; r < 16; ++r) {
        const int rg = rbase + r;
        float* p = (rg < 8) ? (out0 + ((size_t)rg * F) * 1024)
                            : (out1 + ((size_t)(rg - 8) * F) * 1024);
        __stcs(reinterpret_cast<long long*>(p + col), (long long)acc[r]);
    }
}

extern "C" void kernel_launch(void* const* d_in, const int* in_sizes, int n_in,
                              void* d_out, int out_size)
{
    (void)in_sizes; (void)n_in; (void)out_size;

    const float* A2_l11  = (const float*)d_in[0];   // [1024, 9, 1024]
    const float* A2_l22  = (const float*)d_in[1];   // [1024, 25, 1024]
    const float* A2_l33  = (const float*)d_in[2];   // [1024, 49, 1024]
    const float* A3_l111 = (const float*)d_in[3];   // [512, 27, 1024]
    const float* A3_l211 = (const float*)d_in[4];   // [512, 45, 1024]

    const float* CG0_2_l11  = (const float*)d_in[5];
    const float* CG0_2_l22  = (const float*)d_in[6];
    const float* CG0_2_l33  = (const float*)d_in[7];
    const float* CG0_3_l111 = (const float*)d_in[8];
    const float* CG0_3_l211 = (const float*)d_in[9];
    const float* CG1_2_l11  = (const float*)d_in[10];
    const float* CG1_2_l22  = (const float*)d_in[11];
    const float* CG1_2_l33  = (const float*)d_in[12];
    const float* CG1_3_l111 = (const float*)d_in[13];
    const float* CG1_3_l211 = (const float*)d_in[14];

    float* out = (float*)d_out;

    // Output layout: b0 entries then b1 entries, each [R, F, 1024] row-major.
    float* o0_l11  = out + 0;
    float* o0_l22  = out + 8388608;     //  8*1024*1024
    float* o0_l33  = out + 16777216;
    float* o0_l111 = out + 25165824;
    float* o0_l211 = out + 29360128;    // +8*512*1024
    float* o1_l11  = out + 33554432;
    float* o1_l22  = out + 58720256;    // +24*1024*1024
    float* o1_l33  = out + 83886080;
    float* o1_l111 = out + 109051904;
    float* o1_l211 = out + 121634816;   // +24*512*1024

    const dim3 blk(256);
    // grid.x = 2 n-tiles * 2 r-groups = 4 ; grid.y = F
    ace_sym_kernel< 9><<<dim3(4, 1024), blk>>>(A2_l11,  CG0_2_l11,  CG1_2_l11,  o0_l11,  o1_l11,  1024);
    ace_sym_kernel<25><<<dim3(4, 1024), blk>>>(A2_l22,  CG0_2_l22,  CG1_2_l22,  o0_l22,  o1_l22,  1024);
    ace_sym_kernel<49><<<dim3(4, 1024), blk>>>(A2_l33,  CG0_2_l33,  CG1_2_l33,  o0_l33,  o1_l33,  1024);
    ace_sym_kernel<27><<<dim3(4,  512), blk>>>(A3_l111, CG0_3_l111, CG1_3_l111, o0_l111, o1_l111,  512);
    ace_sym_kernel<45><<<dim3(4,  512), blk>>>(A3_l211, CG0_3_l211, CG1_3_l211, o0_l211, o1_l211,  512);
}

// round 9
// speedup vs baseline: 1.4319x; 1.3096x over previous
#include <cuda_runtime.h>
#include <cstdint>

// B[r,f,n] = sum_m CG[r,m] * A[f,m,n]
// f32x2 packs TWO r's per accumulator: acc = {B[2j],B[2j+1]} for one n.
// Coefficients load UNduplicated from shared (1 LDS.128 = 4 coeffs = 2 FFMA2 ops);
// A value is lane-duplicated {a,a} via 2 MOVs per (m,n).
// 16 r x 2 n per thread. r split into 2 groups of 16 across blockIdx.x&1.

using u32 = unsigned int;
using u64 = unsigned long long;

template <int M>
__global__ void __launch_bounds__(256, 3)
ace_sym_kernel(const float* __restrict__ A,
               const float* __restrict__ cg0,   // [8, M]
               const float* __restrict__ cg1,   // [24, M]
               float* __restrict__ out0,        // [8, F, 1024]
               float* __restrict__ out1,        // [24, F, 1024]
               int F)
{
    __shared__ __align__(16) float scg[M * 16];  // [m][16 local r], NOT duplicated

    const int tid   = threadIdx.x;
    const int g     = blockIdx.x & 1;        // r-group: 0 -> r 0..15, 1 -> r 16..31
    const int ntile = blockIdx.x >> 1;       // n-tile: 0 or 1
    const int rbase = g << 4;

    for (int i = tid; i < M * 16; i += 256) {
        const int m  = i >> 4;
        const int r  = i & 15;
        const int rg = rbase + r;
        scg[i] = (rg < 8) ? cg0[rg * M + m] : cg1[(rg - 8) * M + m];
    }
    __syncthreads();

    const int f  = blockIdx.y;
    const int n0 = (ntile * 256 + tid) * 2;  // 2 consecutive n per thread

    // A[f, m, n]: read as u64 pairs {a_n0, a_n1}, stride per m = 512 u64.
    const u64* __restrict__ aptr =
        reinterpret_cast<const u64*>(A + ((size_t)f * M) * 1024 + n0);

    // acc0[j] = {B[rbase+2j][n0],   B[rbase+2j+1][n0]}
    // acc1[j] = {B[rbase+2j][n0+1], B[rbase+2j+1][n0+1]}
    u64 acc0[8], acc1[8];
#pragma unroll
    for (int j = 0; j < 8; ++j) { acc0[j] = 0ull; acc1[j] = 0ull; }

    u64 ring[4];
#pragma unroll
    for (int i = 0; i < 4; ++i) ring[i] = aptr[(size_t)i * 512];

#pragma unroll 4
    for (int m = 0; m < M; ++m) {
        const u64 apair = ring[m & 3];
        if (m + 4 < M) ring[m & 3] = aptr[(size_t)(m + 4) * 512];

        const u32 ax = (u32)apair;          // a at n0
        const u32 ay = (u32)(apair >> 32);  // a at n0+1
        u64 da0, da1;                       // {a,a} duplicated for f32x2
        asm("mov.b64 %0, {%1, %1};" : "=l"(da0) : "r"(ax));
        asm("mov.b64 %0, {%1, %1};" : "=l"(da1) : "r"(ay));

        const ulonglong2* __restrict__ cp =
            reinterpret_cast<const ulonglong2*>(scg + m * 16);
#pragma unroll
        for (int q = 0; q < 4; ++q) {
            const ulonglong2 cc = cp[q];    // cc.x={c[4q],c[4q+1]} cc.y={c[4q+2],c[4q+3]}
            asm("fma.rn.f32x2 %0, %1, %2, %0;" : "+l"(acc0[2 * q])     : "l"(da0), "l"(cc.x));
            asm("fma.rn.f32x2 %0, %1, %2, %0;" : "+l"(acc1[2 * q])     : "l"(da1), "l"(cc.x));
            asm("fma.rn.f32x2 %0, %1, %2, %0;" : "+l"(acc0[2 * q + 1]) : "l"(da0), "l"(cc.y));
            asm("fma.rn.f32x2 %0, %1, %2, %0;" : "+l"(acc1[2 * q + 1]) : "l"(da1), "l"(cc.y));
        }
    }

    // Repack r-major accumulators into n-major u64s -> coalesced STG.64 streams.
    const size_t col = (size_t)f * 1024 + n0;
#pragma unroll
    for (int j = 0; j < 8; ++j) {
        const u64 s0 = (u64)(u32)acc0[j] | ((u64)(u32)acc1[j] << 32);          // row 2j:   {n0, n0+1}
        const u64 s1 = (acc0[j] >> 32)   | (acc1[j] & 0xFFFFFFFF00000000ull);  // row 2j+1: {n0, n0+1}
        const int r0 = rbase + 2 * j;
        float* p0 = (r0 < 8) ? (out0 + ((size_t)r0 * F) * 1024)
                             : (out1 + ((size_t)(r0 - 8) * F) * 1024);
        float* p1 = (r0 + 1 < 8) ? (out0 + ((size_t)(r0 + 1) * F) * 1024)
                                 : (out1 + ((size_t)(r0 + 1 - 8) * F) * 1024);
        __stcs(reinterpret_cast<long long*>(p0 + col), (long long)s0);
        __stcs(reinterpret_cast<long long*>(p1 + col), (long long)s1);
    }
}

extern "C" void kernel_launch(void* const* d_in, const int* in_sizes, int n_in,
                              void* d_out, int out_size)
{
    (void)in_sizes; (void)n_in; (void)out_size;

    const float* A2_l11  = (const float*)d_in[0];   // [1024, 9, 1024]
    const float* A2_l22  = (const float*)d_in[1];   // [1024, 25, 1024]
    const float* A2_l33  = (const float*)d_in[2];   // [1024, 49, 1024]
    const float* A3_l111 = (const float*)d_in[3];   // [512, 27, 1024]
    const float* A3_l211 = (const float*)d_in[4];   // [512, 45, 1024]

    const float* CG0_2_l11  = (const float*)d_in[5];
    const float* CG0_2_l22  = (const float*)d_in[6];
    const float* CG0_2_l33  = (const float*)d_in[7];
    const float* CG0_3_l111 = (const float*)d_in[8];
    const float* CG0_3_l211 = (const float*)d_in[9];
    const float* CG1_2_l11  = (const float*)d_in[10];
    const float* CG1_2_l22  = (const float*)d_in[11];
    const float* CG1_2_l33  = (const float*)d_in[12];
    const float* CG1_3_l111 = (const float*)d_in[13];
    const float* CG1_3_l211 = (const float*)d_in[14];

    float* out = (float*)d_out;

    // Output: b0 entries then b1 entries, each [R, F, 1024] row-major.
    float* o0_l11  = out + 0;
    float* o0_l22  = out + 8388608;     //  8*1024*1024
    float* o0_l33  = out + 16777216;
    float* o0_l111 = out + 25165824;
    float* o0_l211 = out + 29360128;    // +8*512*1024
    float* o1_l11  = out + 33554432;
    float* o1_l22  = out + 58720256;    // +24*1024*1024
    float* o1_l33  = out + 83886080;
    float* o1_l111 = out + 109051904;
    float* o1_l211 = out + 121634816;   // +24*512*1024

    const dim3 blk(256);
    // grid.x = 2 n-tiles * 2 r-groups = 4 ; grid.y = F
    ace_sym_kernel< 9><<<dim3(4, 1024), blk>>>(A2_l11,  CG0_2_l11,  CG1_2_l11,  o0_l11,  o1_l11,  1024);
    ace_sym_kernel<25><<<dim3(4, 1024), blk>>>(A2_l22,  CG0_2_l22,  CG1_2_l22,  o0_l22,  o1_l22,  1024);
    ace_sym_kernel<49><<<dim3(4, 1024), blk>>>(A2_l33,  CG0_2_l33,  CG1_2_l33,  o0_l33,  o1_l33,  1024);
    ace_sym_kernel<27><<<dim3(4,  512), blk>>>(A3_l111, CG0_3_l111, CG1_3_l111, o0_l111, o1_l111,  512);
    ace_sym_kernel<45><<<dim3(4,  512), blk>>>(A3_l211, CG0_3_l211, CG1_3_l211, o0_l211, o1_l211,  512);
}